// round 15
// baseline (speedup 1.0000x reference)
#include <cuda_runtime.h>
#include <cuda_bf16.h>
#include <cuda_fp16.h>
#include <cstdint>
#include <cstddef>

// ---------------- problem constants ----------------
#define Bn   4
#define Cc   128
#define Hh   128
#define Wd   256
#define HW   (Hh*Wd)          // 32768
#define Ff   128
#define CVC  49
#define RAD  24
#define NPIX (Bn*HW)          // 131072
static const size_t NC_ = (size_t)Bn * CVC * HW;  // elements per corr-like tensor

// ---------------- device scratch (static, no allocation) ----------------
__device__ uint16_t g_f1b[(size_t)NPIX * Ff];  // normalized fmap1, fp16 bits, [B][F][H][W]
__device__ uint16_t g_f2b[(size_t)NPIX * Ff];
__device__ float g_M[9 * CVC];                 // [i][j][c], i=volume, j=logit
__device__ float g_beta[3];
// pre-split W images, padded row stride 136 halfwords (matches smem layout)
__device__ uint16_t g_W1h[Ff * 136];
__device__ uint16_t g_W1l[Ff * 136];
__device__ uint16_t g_W2h[Ff * 136];
__device__ uint16_t g_W2l[Ff * 136];

// ---------------- helpers ----------------
__device__ __forceinline__ unsigned long long bcast2(float v) {
    unsigned long long r; asm("mov.b64 %0, {%1,%1};" : "=l"(r) : "f"(v)); return r;
}
__device__ __forceinline__ void unpack2(unsigned long long p, float& lo, float& hi) {
    asm("mov.b64 {%0,%1}, %2;" : "=f"(lo), "=f"(hi) : "l"(p));
}
__device__ __forceinline__ void ffma2(unsigned long long& acc, unsigned long long a, unsigned long long b) {
    asm("fma.rn.f32x2 %0, %1, %2, %0;" : "+l"(acc) : "l"(a), "l"(b));
}
__device__ __forceinline__ void cp16(void* smem_dst, const void* gmem_src) {
    unsigned int s = (unsigned int)__cvta_generic_to_shared(smem_dst);
    asm volatile("cp.async.cg.shared.global [%0], [%1], 16;" :: "r"(s), "l"(gmem_src));
}
__device__ __forceinline__ void cp_commit() { asm volatile("cp.async.commit_group;"); }
template <int N>
__device__ __forceinline__ void cp_wait() { asm volatile("cp.async.wait_group %0;" :: "n"(N)); }

// bf16 warp MMA m16n8k16, A row-major, B col-major, fp32 accum.
__device__ __forceinline__ void mma16816(float* d, const uint32_t* a, const uint32_t* b) {
    asm volatile("mma.sync.aligned.m16n8k16.row.col.f32.bf16.bf16.f32 "
                 "{%0,%1,%2,%3}, {%4,%5,%6,%7}, {%8,%9}, {%0,%1,%2,%3};"
                 : "+f"(d[0]), "+f"(d[1]), "+f"(d[2]), "+f"(d[3])
                 : "r"(a[0]), "r"(a[1]), "r"(a[2]), "r"(a[3]), "r"(b[0]), "r"(b[1]));
}

// split two fp32 into packed-bf16x2 hi and lo words (low half = first element)
__device__ __forceinline__ void split2(float a, float b, uint32_t& h, uint32_t& l) {
    __nv_bfloat16 ha = __float2bfloat16(a), hb = __float2bfloat16(b);
    float ra = a - __bfloat162float(ha), rb = b - __bfloat162float(hb);
    __nv_bfloat16 la = __float2bfloat16(ra), lb = __float2bfloat16(rb);
    h = (uint32_t)*(uint16_t*)&ha | ((uint32_t)*(uint16_t*)&hb << 16);
    l = (uint32_t)*(uint16_t*)&la | ((uint32_t)*(uint16_t*)&lb << 16);
}
__device__ __forceinline__ uint16_t f2hb(float x) {
    __half h = __float2half_rn(x); return *(uint16_t*)&h;
}

// ---------------- prep ----------------
// blocks 0..55: M fold, one warp per output (441 warps);
// block 56: beta; blocks 57..64: W hi/lo split images.
__global__ void prep_kernel(const float* __restrict__ Wgeo, const float* __restrict__ bgeo,
                            const float* __restrict__ Wsel, const float* __restrict__ bsel,
                            const float* __restrict__ WfA,  const float* __restrict__ WfB)
{
    int blk = blockIdx.x, t = threadIdx.x;
    if (blk < 56) {
        int w = blk * 8 + (t >> 5);
        int l = t & 31;
        if (w < 441) {
            int i = w / 147, r = w % 147, j = r / CVC, c = r % CVC;
            float s = 0.f;
            #pragma unroll
            for (int k = 0; k < 3; k++) {
                int m = l + k * 32;
                s += Wsel[j * 288 + i * 96 + m] * Wgeo[m * CVC + c];
            }
            #pragma unroll
            for (int off = 16; off; off >>= 1)
                s += __shfl_xor_sync(0xFFFFFFFF, s, off);
            if (l == 0) g_M[i * 3 * CVC + j * CVC + c] = s;
        }
    } else if (blk == 56) {
        if (t < 3) {
            float s = bsel[t];
            for (int q = 0; q < 288; q++)
                s += Wsel[t * 288 + q] * bgeo[q % 96];
            g_beta[t] = s;
        }
    } else {
        int blk4 = blk - 57;                    // 0..7
        int mat  = blk4 >> 2;
        int part = blk4 & 3;
        const float* src = mat ? WfB : WfA;
        uint16_t* dh = mat ? g_W2h : g_W1h;
        uint16_t* dl = mat ? g_W2l : g_W1l;
        #pragma unroll
        for (int it = 0; it < 16; it++) {
            int idx = part * 4096 + it * 256 + t;   // [o][c]
            int o = idx >> 7, c = idx & 127;
            float v = src[idx];
            __nv_bfloat16 h = __float2bfloat16(v);
            float rv = v - __bfloat162float(h);
            __nv_bfloat16 lo = __float2bfloat16(rv);
            dh[o * 136 + c] = *(uint16_t*)&h;
            dl[o * 136 + c] = *(uint16_t*)&lo;
        }
    }
}

// ---------------- fmap via HMMA, K-pipelined, pre-split W, fp16 output ----------------
#define WH_OFF   0            // uint16[128][136]  34816 B
#define WL_OFF   34816        // uint16[128][136]  34816 B
#define A_OFF    69632        // fp32 [2][32][132] 2x16896 B
#define BIAS_OFF 103424       // fp32[128]
#define SS_OFF   103936       // fp32[128]
#define FM_SMEM_BYTES 104448

extern __shared__ float dynsm[];

__global__ __launch_bounds__(256, 2) void fmap_kernel(
    const float* __restrict__ featA, const float* __restrict__ featB,
    const float* __restrict__ biasA, const float* __restrict__ biasB)
{
    char* smc = (char*)dynsm;
    uint16_t* sWh = (uint16_t*)(smc + WH_OFF);
    uint16_t* sWl = (uint16_t*)(smc + WL_OFF);
    float* sA0   = (float*)(smc + A_OFF);
    float* sA1   = sA0 + 32 * 132;
    float* biasS = (float*)(smc + BIAS_OFF);
    float* ssS   = (float*)(smc + SS_OFF);
    uint16_t* outB = (uint16_t*)smc;          // fp16 stage, stride 136 hw, reuses W region
    float* stg[2] = {sA0, sA1};

    int which = blockIdx.y;
    const float* feat = which ? featB : featA;
    const float* bias = which ? biasB : biasA;
    const uint16_t* gWh = which ? g_W2h : g_W1h;
    const uint16_t* gWl = which ? g_W2l : g_W1l;
    uint16_t* outp = which ? g_f2b : g_f1b;

    int t    = threadIdx.x;
    int wid  = t >> 5, lane = t & 31;
    int gid  = lane >> 2, tig = lane & 3;
    int warp_m = wid & 3, warp_n = wid >> 2;
    int p0  = blockIdx.x * 128;
    int b   = p0 / HW;
    int rem = p0 % HW;
    const float* fbase = feat + (size_t)b * Cc * HW + rem;

    if (t < 128) { biasS[t] = bias[t]; ssS[t] = 0.f; }

    // A chunk 0 prefetch
    #pragma unroll
    for (int it = 0; it < 4; it++) {
        int idx = t + it * 256;
        int c = idx >> 5, q = idx & 31;
        cp16(&sA0[c * 132 + q * 4], &fbase[(size_t)c * HW + q * 4]);
    }
    cp_commit();

    // W hi/lo: linear 16B copies of pre-split images
    #pragma unroll
    for (int it = 0; it < 17; it++) {
        int idx = t + it * 256;                // 0..4351
        int half = idx >= 2176;
        int i = idx - half * 2176;
        int row = i / 17, seg = i % 17;
        if (half) cp16(sWl + row * 136 + seg * 8, gWl + row * 136 + seg * 8);
        else      cp16(sWh + row * 136 + seg * 8, gWh + row * 136 + seg * 8);
    }
    cp_commit();

    float acc[2][8][4];
    #pragma unroll
    for (int mt = 0; mt < 2; mt++)
        #pragma unroll
        for (int nt = 0; nt < 8; nt++)
            #pragma unroll
            for (int r = 0; r < 4; r++) acc[mt][nt][r] = 0.f;

    int row0 = warp_m * 32 + gid;

    #pragma unroll
    for (int ch = 0; ch < 4; ch++) {
        if (ch < 3) {
            float* dst = stg[(ch + 1) & 1];
            const float* src = fbase + (size_t)(ch + 1) * 32 * HW;
            #pragma unroll
            for (int it = 0; it < 4; it++) {
                int idx = t + it * 256;
                int c = idx >> 5, q = idx & 31;
                cp16(&dst[c * 132 + q * 4], &src[(size_t)c * HW + q * 4]);
            }
            cp_commit();
            cp_wait<1>();
        } else {
            cp_wait<0>();
        }
        __syncthreads();

        const float* A = stg[ch & 1];
        #pragma unroll
        for (int ks = 0; ks < 2; ks++) {
            int kb = ks * 16 + 2 * tig;
            uint32_t ah[2][4], al[2][4];
            #pragma unroll
            for (int mt = 0; mt < 2; mt++) {
                int row = row0 + mt * 16;
                float f0 = A[kb * 132 + row],        f1 = A[(kb + 1) * 132 + row];
                float f2 = A[kb * 132 + row + 8],    f3 = A[(kb + 1) * 132 + row + 8];
                float f4 = A[(kb + 8) * 132 + row],  f5 = A[(kb + 9) * 132 + row];
                float f6 = A[(kb + 8) * 132 + row + 8], f7 = A[(kb + 9) * 132 + row + 8];
                split2(f0, f1, ah[mt][0], al[mt][0]);
                split2(f2, f3, ah[mt][1], al[mt][1]);
                split2(f4, f5, ah[mt][2], al[mt][2]);
                split2(f6, f7, ah[mt][3], al[mt][3]);
            }
            int kw = ch * 32 + kb;
            #pragma unroll
            for (int nt = 0; nt < 8; nt++) {
                int orow = warp_n * 64 + nt * 8 + gid;
                uint32_t wh[2], wl[2];
                wh[0] = *(const uint32_t*)(sWh + orow * 136 + kw);
                wh[1] = *(const uint32_t*)(sWh + orow * 136 + kw + 8);
                wl[0] = *(const uint32_t*)(sWl + orow * 136 + kw);
                wl[1] = *(const uint32_t*)(sWl + orow * 136 + kw + 8);
                mma16816(acc[0][nt], ah[0], wh);
                mma16816(acc[0][nt], al[0], wh);
                mma16816(acc[0][nt], ah[0], wl);
                mma16816(acc[1][nt], ah[1], wh);
                mma16816(acc[1][nt], al[1], wh);
                mma16816(acc[1][nt], ah[1], wl);
            }
        }
        __syncthreads();
    }

    // ---- epilogue: bias, per-pixel L2 norm, fp16-staged coalesced stores ----
    #pragma unroll
    for (int nt = 0; nt < 8; nt++) {
        int ob2 = warp_n * 64 + nt * 8 + 2 * tig;
        float bi0 = biasS[ob2], bi1 = biasS[ob2 + 1];
        #pragma unroll
        for (int mt = 0; mt < 2; mt++) {
            acc[mt][nt][0] += bi0; acc[mt][nt][1] += bi1;
            acc[mt][nt][2] += bi0; acc[mt][nt][3] += bi1;
        }
    }

    float s0[2] = {0.f, 0.f}, s1[2] = {0.f, 0.f};
    #pragma unroll
    for (int mt = 0; mt < 2; mt++)
        #pragma unroll
        for (int nt = 0; nt < 8; nt++) {
            s0[mt] += acc[mt][nt][0] * acc[mt][nt][0] + acc[mt][nt][1] * acc[mt][nt][1];
            s1[mt] += acc[mt][nt][2] * acc[mt][nt][2] + acc[mt][nt][3] * acc[mt][nt][3];
        }
    #pragma unroll
    for (int off = 1; off <= 2; off <<= 1) {
        s0[0] += __shfl_xor_sync(0xFFFFFFFF, s0[0], off);
        s0[1] += __shfl_xor_sync(0xFFFFFFFF, s0[1], off);
        s1[0] += __shfl_xor_sync(0xFFFFFFFF, s1[0], off);
        s1[1] += __shfl_xor_sync(0xFFFFFFFF, s1[1], off);
    }
    if (tig == 0) {
        #pragma unroll
        for (int mt = 0; mt < 2; mt++) {
            int px = warp_m * 32 + mt * 16 + gid;
            atomicAdd(&ssS[px], s0[mt]);
            atomicAdd(&ssS[px + 8], s1[mt]);
        }
    }
    __syncthreads();
    if (t < 128) ssS[t] = 1.f / (sqrtf(ssS[t]) + 1e-8f);
    __syncthreads();

    #pragma unroll
    for (int mt = 0; mt < 2; mt++) {
        int px = warp_m * 32 + mt * 16 + gid;
        float iv0 = ssS[px], iv1 = ssS[px + 8];
        #pragma unroll
        for (int nt = 0; nt < 8; nt++) {
            int o = warp_n * 64 + nt * 8 + 2 * tig;
            outB[o * 136 + px]           = f2hb(acc[mt][nt][0] * iv0);
            outB[(o + 1) * 136 + px]     = f2hb(acc[mt][nt][1] * iv0);
            outB[o * 136 + px + 8]       = f2hb(acc[mt][nt][2] * iv1);
            outB[(o + 1) * 136 + px + 8] = f2hb(acc[mt][nt][3] * iv1);
        }
    }
    __syncthreads();

    #pragma unroll
    for (int it = 0; it < 8; it++) {
        int idx = t + it * 256;                // 2048 uint4 (8 fp16 each)
        int o = idx >> 4, seg = idx & 15;
        uint4 v = *(const uint4*)(outB + o * 136 + seg * 8);
        *(uint4*)(outp + ((size_t)b * Ff + o) * HW + rem + seg * 8) = v;
    }
}

// ---------------- fused correlation + selector, fp16 inputs, 4-quarter pipeline ----------------
// smem floats: work_s1 @0 (2176, stride 68), work_s2 @2176 (3712, stride 116),
// cvS @5888 (9408), wsm @15296 (192), Msm @15488 (441), beta @15929,
// fp16 stages @15936 (2 x 2816 floats: s1b 2048hw + s2b 3584hw). outS reuses @0.
#define CS_STG_F 2816
#define CS_SMEM_BYTES ((15936 + 2 * CS_STG_F) * 4)

__global__ __launch_bounds__(224) void corrsel_kernel(const float* __restrict__ cv0,
                                                      const float* __restrict__ cv1,
                                                      const float* __restrict__ cv2,
                                                      float* __restrict__ out)
{
    float* work1 = dynsm;
    float* work2 = dynsm + 2176;
    float* cvS   = dynsm + 5888;
    float* wsm   = dynsm + 15296;
    float* Msm   = dynsm + 15488;
    float* betaS = dynsm + 15929;
    uint16_t* stgb = (uint16_t*)(dynsm + 15936);
    float* outS  = dynsm;

    int t   = threadIdx.x;
    int blk = blockIdx.x;
    int bh  = blk >> 2;
    int x0  = (blk & 3) * 64;
    int b   = bh / Hh, h = bh % Hh;

    // group 1: cv tiles
    for (int idx = t; idx < 3 * CVC * 16; idx += 224) {
        int v = idx / (CVC * 16);
        int r = idx - v * (CVC * 16);
        int c = r >> 4, q = r & 15;
        const float* src = (v == 0 ? cv0 : (v == 1 ? cv1 : cv2));
        cp16(&cvS[(v * CVC + c) * 64 + q * 4],
             &src[((size_t)(b * CVC + c) * Hh + h) * Wd + x0 + q * 4]);
    }
    cp_commit();

    const uint16_t* f1 = g_f1b + (size_t)b * Ff * HW + (size_t)h * Wd;
    const uint16_t* f2 = g_f2b + (size_t)b * Ff * HW + (size_t)h * Wd;

    auto load_q = [&](int qq, int s) {
        uint16_t* s1b = stgb + s * 2 * CS_STG_F;       // 2816 floats = 5632 hw
        uint16_t* s2b = s1b + 2048;
        int cb = qq * 32;
        for (int idx = t; idx < 256; idx += 224) {     // 32 ch x 8 chunks (8 fp16)
            int o = idx >> 3, q8 = idx & 7;
            cp16(s1b + o * 64 + q8 * 8, f1 + (size_t)(cb + o) * HW + x0 + q8 * 8);
        }
        for (int idx = t; idx < 448; idx += 224) {     // 32 ch x 14 chunks
            int o = idx / 14, q8 = idx % 14;
            int xg = x0 - RAD + q8 * 8;
            if (xg >= 0 && xg <= Wd - 8)
                cp16(s2b + o * 112 + q8 * 8, f2 + (size_t)(cb + o) * HW + xg);
            else {
                uint4 z = make_uint4(0, 0, 0, 0);
                *(uint4*)(s2b + o * 112 + q8 * 8) = z;
            }
        }
        cp_commit();
    };

    load_q(0, 0);                                      // group 2

    int xt = t & 15, j = t >> 4;       // j 0..13 (j==13 -> load-only helper)
    bool active = (j < 13);

    unsigned long long acc[4][2];
    #pragma unroll
    for (int i = 0; i < 4; i++) { acc[i][0] = 0ULL; acc[i][1] = 0ULL; }

    #pragma unroll
    for (int qq = 0; qq < 4; qq++) {
        if (qq < 3) { load_q(qq + 1, (qq + 1) & 1); cp_wait<1>(); }
        else        { cp_wait<0>(); }
        __syncthreads();

        // convert fp16 stage -> fp32 working buffers
        {
            const uint32_t* s1u = (const uint32_t*)(stgb + (qq & 1) * 2 * CS_STG_F);
            const uint32_t* s2u = s1u + 1024;
            for (int i = t; i < 2816; i += 224) {
                if (i < 1024) {
                    int o = i >> 5, p2 = i & 31;
                    uint32_t u = s1u[i];
                    float2 f = __half22float2(*(const __half2*)&u);
                    work1[o * 68 + 2 * p2]     = f.x;
                    work1[o * 68 + 2 * p2 + 1] = f.y;
                } else {
                    int ii = i - 1024;
                    int o = ii / 56, p2 = ii % 56;
                    uint32_t u = s2u[ii];
                    float2 f = __half22float2(*(const __half2*)&u);
                    work2[o * 116 + 2 * p2]     = f.x;
                    work2[o * 116 + 2 * p2 + 1] = f.y;
                }
            }
        }
        __syncthreads();

        if (active) {
            #pragma unroll 4
            for (int o = 0; o < 32; o++) {
                float4 a = *(const float4*)&work1[o * 68 + 4 * xt];
                ulonglong2 bb = *(const ulonglong2*)&work2[o * 116 + 4 * (xt + j)];
                float av[4] = {a.x, a.y, a.z, a.w};
                #pragma unroll
                for (int i = 0; i < 4; i++) {
                    unsigned long long aa = bcast2(av[i]);
                    ffma2(acc[i][0], aa, bb.x);
                    ffma2(acc[i][1], aa, bb.y);
                }
            }
        }
        __syncthreads();
    }

    // ---- stage corr tile into outS; load M/beta ----
    if (active) {
        #pragma unroll
        for (int i = 0; i < 4; i++) {
            float vals[4];
            unpack2(acc[i][0], vals[0], vals[1]);
            unpack2(acc[i][1], vals[2], vals[3]);
            #pragma unroll
            for (int ip = 0; ip < 4; ip++) {
                int k = 48 - 4 * j + i - ip;
                if (k >= 0 && k <= 48)
                    outS[k * 64 + 4 * xt + i] = vals[ip];
            }
        }
    }
    for (int i = t; i < 9 * CVC; i += 224) Msm[i] = g_M[i];
    if (t < 3) betaS[t] = g_beta[t];
    __syncthreads();

    // ---- folded logits (192 threads: 3 logits x 64 px) ----
    if (t < 192) {
        int j2 = t >> 6;
        int x  = t & 63;
        float l = betaS[j2];
        const float* M0 = Msm + 0 * 3 * CVC + j2 * CVC;
        const float* M1 = Msm + 1 * 3 * CVC + j2 * CVC;
        const float* M2 = Msm + 2 * 3 * CVC + j2 * CVC;
        #pragma unroll 7
        for (int c = 0; c < CVC; c++) {
            l = fmaf(M0[c], cvS[(0 * CVC + c) * 64 + x],
                fmaf(M1[c], cvS[(1 * CVC + c) * 64 + x],
                fmaf(M2[c], cvS[(2 * CVC + c) * 64 + x], l)));
        }
        wsm[j2 * 64 + x] = l;
    }
    __syncthreads();

    // ---- softmax ----
    if (t < 64) {
        float l0 = wsm[t], l1 = wsm[64 + t], l2 = wsm[128 + t];
        float m  = fmaxf(l0, fmaxf(l1, l2));
        float e0 = expf(l0 - m), e1 = expf(l1 - m), e2 = expf(l2 - m);
        float inv = 1.f / (e0 + e1 + e2);
        float w0 = e0 * inv, w1 = e1 * inv, w2 = e2 * inv;
        wsm[t] = w0; wsm[64 + t] = w1; wsm[128 + t] = w2;
        float* wout = out + 2 * NC_ + ((size_t)b * 3 * Hh + h) * Wd + x0 + t;
        wout[0]              = w0;
        wout[(size_t)HW]     = w1;
        wout[(size_t)2 * HW] = w2;
    }
    __syncthreads();

    // ---- final = corr + w·cv ; write final + init_corr ----
    for (int idx = t; idx < CVC * 16; idx += 224) {
        int k = idx >> 4, q = idx & 15;
        float4 corr4 = *(const float4*)&outS[k * 64 + q * 4];
        float4 a0 = *(const float4*)&cvS[(0 * CVC + k) * 64 + q * 4];
        float4 a1 = *(const float4*)&cvS[(1 * CVC + k) * 64 + q * 4];
        float4 a2 = *(const float4*)&cvS[(2 * CVC + k) * 64 + q * 4];
        float4 w0 = *(const float4*)&wsm[0 * 64 + q * 4];
        float4 w1 = *(const float4*)&wsm[1 * 64 + q * 4];
        float4 w2 = *(const float4*)&wsm[2 * 64 + q * 4];
        float4 fin;
        fin.x = corr4.x + fmaf(w0.x, a0.x, fmaf(w1.x, a1.x, w2.x * a2.x));
        fin.y = corr4.y + fmaf(w0.y, a0.y, fmaf(w1.y, a1.y, w2.y * a2.y));
        fin.z = corr4.z + fmaf(w0.z, a0.z, fmaf(w1.z, a1.z, w2.z * a2.z));
        fin.w = corr4.w + fmaf(w0.w, a0.w, fmaf(w1.w, a1.w, w2.w * a2.w));
        size_t off = ((size_t)(b * CVC + k) * Hh + h) * Wd + x0 + q * 4;
        *(float4*)&out[off]       = fin;
        *(float4*)&out[NC_ + off] = corr4;
    }
}

// ---------------- launch ----------------
extern "C" void kernel_launch(void* const* d_in, const int* in_sizes, int n_in,
                              void* d_out, int out_size)
{
    const float* feat_l1 = (const float*)d_in[0];
    const float* feat_r1 = (const float*)d_in[1];
    const float* cv0     = (const float*)d_in[2];
    const float* cv1     = (const float*)d_in[3];
    const float* cv2     = (const float*)d_in[4];
    const float* W_f1    = (const float*)d_in[5];
    const float* b_f1    = (const float*)d_in[6];
    const float* W_f2    = (const float*)d_in[7];
    const float* b_f2    = (const float*)d_in[8];
    const float* W_geo   = (const float*)d_in[9];
    const float* b_geo   = (const float*)d_in[10];
    const float* W_sel   = (const float*)d_in[11];
    const float* b_sel   = (const float*)d_in[12];
    float* out = (float*)d_out;

    prep_kernel<<<65, 256>>>(W_geo, b_geo, W_sel, b_sel, W_f1, W_f2);

    static int fm_set = 0;
    if (!fm_set) {
        cudaFuncSetAttribute(fmap_kernel, cudaFuncAttributeMaxDynamicSharedMemorySize, FM_SMEM_BYTES);
        fm_set = 1;
    }
    fmap_kernel<<<dim3(NPIX / 128, 2), 256, FM_SMEM_BYTES>>>(feat_l1, feat_r1, b_f1, b_f2);

    static int cs_set = 0;
    if (!cs_set) {
        cudaFuncSetAttribute(corrsel_kernel, cudaFuncAttributeMaxDynamicSharedMemorySize, CS_SMEM_BYTES);
        cs_set = 1;
    }
    corrsel_kernel<<<Bn * Hh * (Wd / 64), 224, CS_SMEM_BYTES>>>(cv0, cv1, cv2, out);
}

// round 16
// speedup vs baseline: 1.5161x; 1.5161x over previous
#include <cuda_runtime.h>
#include <cuda_bf16.h>
#include <cuda_fp16.h>
#include <cstdint>
#include <cstddef>

// ---------------- problem constants ----------------
#define Bn   4
#define Cc   128
#define Hh   128
#define Wd   256
#define HW   (Hh*Wd)          // 32768
#define Ff   128
#define CVC  49
#define RAD  24
#define NPIX (Bn*HW)          // 131072
static const size_t NC_ = (size_t)Bn * CVC * HW;  // elements per corr-like tensor

// ---------------- device scratch (static, no allocation) ----------------
// normalized fmaps, fp16 bits, PIXEL-major [B][H][W][F]
__device__ uint16_t g_f1b[(size_t)NPIX * Ff];
__device__ uint16_t g_f2b[(size_t)NPIX * Ff];
__device__ float g_M[9 * CVC];                 // [i][j][c], i=volume, j=logit
__device__ float g_beta[3];
// pre-split W images, padded row stride 136 halfwords (matches smem layout)
__device__ uint16_t g_W1h[Ff * 136];
__device__ uint16_t g_W1l[Ff * 136];
__device__ uint16_t g_W2h[Ff * 136];
__device__ uint16_t g_W2l[Ff * 136];

// ---------------- helpers ----------------
__device__ __forceinline__ void cp16(void* smem_dst, const void* gmem_src) {
    unsigned int s = (unsigned int)__cvta_generic_to_shared(smem_dst);
    asm volatile("cp.async.cg.shared.global [%0], [%1], 16;" :: "r"(s), "l"(gmem_src));
}
__device__ __forceinline__ void cp_commit() { asm volatile("cp.async.commit_group;"); }
template <int N>
__device__ __forceinline__ void cp_wait() { asm volatile("cp.async.wait_group %0;" :: "n"(N)); }

// bf16 warp MMA m16n8k16 (fmap GEMM), A row-major, B col-major, fp32 accum.
__device__ __forceinline__ void mma16816(float* d, const uint32_t* a, const uint32_t* b) {
    asm volatile("mma.sync.aligned.m16n8k16.row.col.f32.bf16.bf16.f32 "
                 "{%0,%1,%2,%3}, {%4,%5,%6,%7}, {%8,%9}, {%0,%1,%2,%3};"
                 : "+f"(d[0]), "+f"(d[1]), "+f"(d[2]), "+f"(d[3])
                 : "r"(a[0]), "r"(a[1]), "r"(a[2]), "r"(a[3]), "r"(b[0]), "r"(b[1]));
}
// fp16 warp MMA m16n8k16 (corr Gram), fp32 accum.
__device__ __forceinline__ void mma16816h(float* d, const uint32_t* a, const uint32_t* b) {
    asm volatile("mma.sync.aligned.m16n8k16.row.col.f32.f16.f16.f32 "
                 "{%0,%1,%2,%3}, {%4,%5,%6,%7}, {%8,%9}, {%0,%1,%2,%3};"
                 : "+f"(d[0]), "+f"(d[1]), "+f"(d[2]), "+f"(d[3])
                 : "r"(a[0]), "r"(a[1]), "r"(a[2]), "r"(a[3]), "r"(b[0]), "r"(b[1]));
}

// split two fp32 into packed-bf16x2 hi and lo words (low half = first element)
__device__ __forceinline__ void split2(float a, float b, uint32_t& h, uint32_t& l) {
    __nv_bfloat16 ha = __float2bfloat16(a), hb = __float2bfloat16(b);
    float ra = a - __bfloat162float(ha), rb = b - __bfloat162float(hb);
    __nv_bfloat16 la = __float2bfloat16(ra), lb = __float2bfloat16(rb);
    h = (uint32_t)*(uint16_t*)&ha | ((uint32_t)*(uint16_t*)&hb << 16);
    l = (uint32_t)*(uint16_t*)&la | ((uint32_t)*(uint16_t*)&lb << 16);
}
__device__ __forceinline__ uint32_t pack2h(float a, float b) {
    __half2 h = __floats2half2_rn(a, b); return *(uint32_t*)&h;
}

// ---------------- prep ----------------
// blocks 0..55: M fold, one warp per output (441 warps);
// block 56: beta; blocks 57..64: W hi/lo split images.
__global__ void prep_kernel(const float* __restrict__ Wgeo, const float* __restrict__ bgeo,
                            const float* __restrict__ Wsel, const float* __restrict__ bsel,
                            const float* __restrict__ WfA,  const float* __restrict__ WfB)
{
    int blk = blockIdx.x, t = threadIdx.x;
    if (blk < 56) {
        int w = blk * 8 + (t >> 5);
        int l = t & 31;
        if (w < 441) {
            int i = w / 147, r = w % 147, j = r / CVC, c = r % CVC;
            float s = 0.f;
            #pragma unroll
            for (int k = 0; k < 3; k++) {
                int m = l + k * 32;
                s += Wsel[j * 288 + i * 96 + m] * Wgeo[m * CVC + c];
            }
            #pragma unroll
            for (int off = 16; off; off >>= 1)
                s += __shfl_xor_sync(0xFFFFFFFF, s, off);
            if (l == 0) g_M[i * 3 * CVC + j * CVC + c] = s;
        }
    } else if (blk == 56) {
        if (t < 3) {
            float s = bsel[t];
            for (int q = 0; q < 288; q++)
                s += Wsel[t * 288 + q] * bgeo[q % 96];
            g_beta[t] = s;
        }
    } else {
        int blk4 = blk - 57;                    // 0..7
        int mat  = blk4 >> 2;
        int part = blk4 & 3;
        const float* src = mat ? WfB : WfA;
        uint16_t* dh = mat ? g_W2h : g_W1h;
        uint16_t* dl = mat ? g_W2l : g_W1l;
        #pragma unroll
        for (int it = 0; it < 16; it++) {
            int idx = part * 4096 + it * 256 + t;   // [o][c]
            int o = idx >> 7, c = idx & 127;
            float v = src[idx];
            __nv_bfloat16 h = __float2bfloat16(v);
            float rv = v - __bfloat162float(h);
            __nv_bfloat16 lo = __float2bfloat16(rv);
            dh[o * 136 + c] = *(uint16_t*)&h;
            dl[o * 136 + c] = *(uint16_t*)&lo;
        }
    }
}

// ---------------- fmap via HMMA, K-pipelined, pre-split W, fp16 pixel-major out ----------------
#define WH_OFF   0            // uint16[128][136]  34816 B
#define WL_OFF   34816        // uint16[128][136]  34816 B
#define A_OFF    69632        // fp32 [2][32][132] 2x16896 B
#define BIAS_OFF 103424       // fp32[128]
#define SS_OFF   103936       // fp32[128]
#define FM_SMEM_BYTES 104448

extern __shared__ float dynsm[];

__global__ __launch_bounds__(256, 2) void fmap_kernel(
    const float* __restrict__ featA, const float* __restrict__ featB,
    const float* __restrict__ biasA, const float* __restrict__ biasB)
{
    char* smc = (char*)dynsm;
    uint16_t* sWh = (uint16_t*)(smc + WH_OFF);
    uint16_t* sWl = (uint16_t*)(smc + WL_OFF);
    float* sA0   = (float*)(smc + A_OFF);
    float* sA1   = sA0 + 32 * 132;
    float* biasS = (float*)(smc + BIAS_OFF);
    float* ssS   = (float*)(smc + SS_OFF);
    uint16_t* outB = (uint16_t*)smc;          // fp16 stage [px][o], stride 136, reuses W region
    float* stg[2] = {sA0, sA1};

    int which = blockIdx.y;
    const float* feat = which ? featB : featA;
    const float* bias = which ? biasB : biasA;
    const uint16_t* gWh = which ? g_W2h : g_W1h;
    const uint16_t* gWl = which ? g_W2l : g_W1l;
    uint16_t* outp = which ? g_f2b : g_f1b;

    int t    = threadIdx.x;
    int wid  = t >> 5, lane = t & 31;
    int gid  = lane >> 2, tig = lane & 3;
    int warp_m = wid & 3, warp_n = wid >> 2;
    int p0  = blockIdx.x * 128;
    int b   = p0 / HW;
    int rem = p0 % HW;
    const float* fbase = feat + (size_t)b * Cc * HW + rem;

    if (t < 128) { biasS[t] = bias[t]; ssS[t] = 0.f; }

    // A chunk 0 prefetch
    #pragma unroll
    for (int it = 0; it < 4; it++) {
        int idx = t + it * 256;
        int c = idx >> 5, q = idx & 31;
        cp16(&sA0[c * 132 + q * 4], &fbase[(size_t)c * HW + q * 4]);
    }
    cp_commit();

    // W hi/lo: linear 16B copies of pre-split images
    #pragma unroll
    for (int it = 0; it < 17; it++) {
        int idx = t + it * 256;                // 0..4351
        int half = idx >= 2176;
        int i = idx - half * 2176;
        int row = i / 17, seg = i % 17;
        if (half) cp16(sWl + row * 136 + seg * 8, gWl + row * 136 + seg * 8);
        else      cp16(sWh + row * 136 + seg * 8, gWh + row * 136 + seg * 8);
    }
    cp_commit();

    float acc[2][8][4];
    #pragma unroll
    for (int mt = 0; mt < 2; mt++)
        #pragma unroll
        for (int nt = 0; nt < 8; nt++)
            #pragma unroll
            for (int r = 0; r < 4; r++) acc[mt][nt][r] = 0.f;

    int row0 = warp_m * 32 + gid;

    #pragma unroll
    for (int ch = 0; ch < 4; ch++) {
        if (ch < 3) {
            float* dst = stg[(ch + 1) & 1];
            const float* src = fbase + (size_t)(ch + 1) * 32 * HW;
            #pragma unroll
            for (int it = 0; it < 4; it++) {
                int idx = t + it * 256;
                int c = idx >> 5, q = idx & 31;
                cp16(&dst[c * 132 + q * 4], &src[(size_t)c * HW + q * 4]);
            }
            cp_commit();
            cp_wait<1>();
        } else {
            cp_wait<0>();
        }
        __syncthreads();

        const float* A = stg[ch & 1];
        #pragma unroll
        for (int ks = 0; ks < 2; ks++) {
            int kb = ks * 16 + 2 * tig;
            uint32_t ah[2][4], al[2][4];
            #pragma unroll
            for (int mt = 0; mt < 2; mt++) {
                int row = row0 + mt * 16;
                float f0 = A[kb * 132 + row],        f1 = A[(kb + 1) * 132 + row];
                float f2 = A[kb * 132 + row + 8],    f3 = A[(kb + 1) * 132 + row + 8];
                float f4 = A[(kb + 8) * 132 + row],  f5 = A[(kb + 9) * 132 + row];
                float f6 = A[(kb + 8) * 132 + row + 8], f7 = A[(kb + 9) * 132 + row + 8];
                split2(f0, f1, ah[mt][0], al[mt][0]);
                split2(f2, f3, ah[mt][1], al[mt][1]);
                split2(f4, f5, ah[mt][2], al[mt][2]);
                split2(f6, f7, ah[mt][3], al[mt][3]);
            }
            int kw = ch * 32 + kb;
            #pragma unroll
            for (int nt = 0; nt < 8; nt++) {
                int orow = warp_n * 64 + nt * 8 + gid;
                uint32_t wh[2], wl[2];
                wh[0] = *(const uint32_t*)(sWh + orow * 136 + kw);
                wh[1] = *(const uint32_t*)(sWh + orow * 136 + kw + 8);
                wl[0] = *(const uint32_t*)(sWl + orow * 136 + kw);
                wl[1] = *(const uint32_t*)(sWl + orow * 136 + kw + 8);
                mma16816(acc[0][nt], ah[0], wh);
                mma16816(acc[0][nt], al[0], wh);
                mma16816(acc[0][nt], ah[0], wl);
                mma16816(acc[1][nt], ah[1], wh);
                mma16816(acc[1][nt], al[1], wh);
                mma16816(acc[1][nt], ah[1], wl);
            }
        }
        __syncthreads();
    }

    // ---- epilogue: bias, per-pixel L2 norm, fp16 pixel-major staged stores ----
    #pragma unroll
    for (int nt = 0; nt < 8; nt++) {
        int ob2 = warp_n * 64 + nt * 8 + 2 * tig;
        float bi0 = biasS[ob2], bi1 = biasS[ob2 + 1];
        #pragma unroll
        for (int mt = 0; mt < 2; mt++) {
            acc[mt][nt][0] += bi0; acc[mt][nt][1] += bi1;
            acc[mt][nt][2] += bi0; acc[mt][nt][3] += bi1;
        }
    }

    float s0[2] = {0.f, 0.f}, s1[2] = {0.f, 0.f};
    #pragma unroll
    for (int mt = 0; mt < 2; mt++)
        #pragma unroll
        for (int nt = 0; nt < 8; nt++) {
            s0[mt] += acc[mt][nt][0] * acc[mt][nt][0] + acc[mt][nt][1] * acc[mt][nt][1];
            s1[mt] += acc[mt][nt][2] * acc[mt][nt][2] + acc[mt][nt][3] * acc[mt][nt][3];
        }
    #pragma unroll
    for (int off = 1; off <= 2; off <<= 1) {
        s0[0] += __shfl_xor_sync(0xFFFFFFFF, s0[0], off);
        s0[1] += __shfl_xor_sync(0xFFFFFFFF, s0[1], off);
        s1[0] += __shfl_xor_sync(0xFFFFFFFF, s1[0], off);
        s1[1] += __shfl_xor_sync(0xFFFFFFFF, s1[1], off);
    }
    if (tig == 0) {
        #pragma unroll
        for (int mt = 0; mt < 2; mt++) {
            int px = warp_m * 32 + mt * 16 + gid;
            atomicAdd(&ssS[px], s0[mt]);
            atomicAdd(&ssS[px + 8], s1[mt]);
        }
    }
    __syncthreads();
    if (t < 128) ssS[t] = 1.f / (sqrtf(ssS[t]) + 1e-8f);
    __syncthreads();

    #pragma unroll
    for (int mt = 0; mt < 2; mt++) {
        int px = warp_m * 32 + mt * 16 + gid;
        float iv0 = ssS[px], iv1 = ssS[px + 8];
        #pragma unroll
        for (int nt = 0; nt < 8; nt++) {
            int o = warp_n * 64 + nt * 8 + 2 * tig;     // even
            *(uint32_t*)(outB + px * 136 + o) =
                pack2h(acc[mt][nt][0] * iv0, acc[mt][nt][1] * iv0);
            *(uint32_t*)(outB + (px + 8) * 136 + o) =
                pack2h(acc[mt][nt][2] * iv1, acc[mt][nt][3] * iv1);
        }
    }
    __syncthreads();

    #pragma unroll
    for (int it = 0; it < 8; it++) {
        int idx = t + it * 256;                // 2048 uint4 (8 fp16 each)
        int px = idx >> 4, seg = idx & 15;
        uint4 v = *(const uint4*)(outB + px * 136 + seg * 8);
        *(uint4*)(outp + ((size_t)p0 + px) * Ff + seg * 8) = v;
    }
}

// ---------------- fused correlation(HMMA) + selector ----------------
// smem floats: sA fp16 64x136 @0 (4352f), sB fp16 112x136 @4352 (7616f),
// cvS @11968 (9408), wsm @21376 (192), Msm @21568 (441), beta @22009.
// outS (3136f) reuses sA after MMA.
#define CS_SB  4352
#define CS_CV  11968
#define CS_WS  21376
#define CS_MS  21568
#define CS_BT  22009
#define CS_SMEM_BYTES (22012 * 4)

__global__ __launch_bounds__(256, 2) void corrsel_kernel(const float* __restrict__ cv0,
                                                         const float* __restrict__ cv1,
                                                         const float* __restrict__ cv2,
                                                         float* __restrict__ out)
{
    uint16_t* sA = (uint16_t*)dynsm;
    uint16_t* sB = (uint16_t*)(dynsm + CS_SB);
    float* cvS   = dynsm + CS_CV;
    float* wsm   = dynsm + CS_WS;
    float* Msm   = dynsm + CS_MS;
    float* betaS = dynsm + CS_BT;
    float* outS  = dynsm;

    int t   = threadIdx.x;
    int blk = blockIdx.x;
    int bh  = blk >> 2;
    int x0  = (blk & 3) * 64;
    int b   = bh / Hh, h = bh % Hh;

    const uint16_t* f1 = g_f1b + ((size_t)bh * Wd + x0) * Ff;   // pixel-major rows
    const uint16_t* f2 = g_f2b + (size_t)bh * Wd * Ff;

    // group 1: A + B fp16 tiles
    for (int idx = t; idx < 1024; idx += 256) {        // 64 px x 16 seg
        int px = idx >> 4, seg = idx & 15;
        cp16(sA + px * 136 + seg * 8, f1 + (size_t)px * Ff + seg * 8);
    }
    for (int idx = t; idx < 1792; idx += 256) {        // 112 r x 16 seg
        int r = idx >> 4, seg = idx & 15;
        int xg = x0 - RAD + r;
        if (xg >= 0 && xg < Wd)
            cp16(sB + r * 136 + seg * 8, f2 + (size_t)xg * Ff + seg * 8);
        else
            *(uint4*)(sB + r * 136 + seg * 8) = make_uint4(0, 0, 0, 0);
    }
    cp_commit();

    // group 2: cv tiles
    for (int idx = t; idx < 3 * CVC * 16; idx += 256) {
        int v = idx / (CVC * 16);
        int r = idx - v * (CVC * 16);
        int c = r >> 4, q = r & 15;
        const float* src = (v == 0 ? cv0 : (v == 1 ? cv1 : cv2));
        cp16(&cvS[(v * CVC + c) * 64 + q * 4],
             &src[((size_t)(b * CVC + c) * Hh + h) * Wd + x0 + q * 4]);
    }
    cp_commit();

    // M/beta plain loads (region not reused)
    for (int i = t; i < 9 * CVC; i += 256) Msm[i] = g_M[i];
    if (t < 3) betaS[t] = g_beta[t];

    cp_wait<1>();          // A+B tiles resident
    __syncthreads();

    // ---- Gram via fp16 HMMA: out[xl, r] = sum_ch A[xl][ch] * B[r][ch] ----
    int wid = t >> 5, lane = t & 31;
    int gid = lane >> 2, tig = lane & 3;
    int wm = wid & 3, wn = wid >> 2;
    int m0 = wm * 16;

    float acc[4][4];
    #pragma unroll
    for (int nt = 0; nt < 4; nt++)
        #pragma unroll
        for (int r = 0; r < 4; r++) acc[nt][r] = 0.f;

    #pragma unroll
    for (int kt = 0; kt < 8; kt++) {
        int kb = kt * 16 + 2 * tig;
        uint32_t a[4];
        a[0] = *(const uint32_t*)(sA + (m0 + gid) * 136 + kb);
        a[1] = *(const uint32_t*)(sA + (m0 + gid + 8) * 136 + kb);
        a[2] = *(const uint32_t*)(sA + (m0 + gid) * 136 + kb + 8);
        a[3] = *(const uint32_t*)(sA + (m0 + gid + 8) * 136 + kb + 8);
        #pragma unroll
        for (int nt = 0; nt < 4; nt++) {
            int rb = m0 + wn * 32 + nt * 8;
            uint32_t bf[2];
            bf[0] = *(const uint32_t*)(sB + (rb + gid) * 136 + kb);
            bf[1] = *(const uint32_t*)(sB + (rb + gid) * 136 + kb + 8);
            mma16816h(acc[nt], a, bf);
        }
    }
    __syncthreads();       // sA reads done; outS may overwrite

    // scatter to outS[k*64 + xl], k = xl + 48 - r
    #pragma unroll
    for (int nt = 0; nt < 4; nt++) {
        int rb = m0 + wn * 32 + nt * 8 + 2 * tig;
        int xl0 = m0 + gid;
        int k00 = xl0 + 48 - rb;        // c0: (xl0, rb)
        if (k00 >= 0 && k00 <= 48)      outS[k00 * 64 + xl0]           = acc[nt][0];
        if (k00 - 1 >= 0 && k00 - 1 <= 48) outS[(k00 - 1) * 64 + xl0]  = acc[nt][1];
        int k20 = k00 + 8;              // c2: (xl0+8, rb)
        if (k20 >= 0 && k20 <= 48)      outS[k20 * 64 + xl0 + 8]       = acc[nt][2];
        if (k20 - 1 >= 0 && k20 - 1 <= 48) outS[(k20 - 1) * 64 + xl0 + 8] = acc[nt][3];
    }
    cp_wait<0>();          // cv resident
    __syncthreads();

    // ---- folded logits (192 threads: 3 logits x 64 px) ----
    if (t < 192) {
        int j2 = t >> 6;
        int x  = t & 63;
        float l = betaS[j2];
        const float* M0 = Msm + 0 * 3 * CVC + j2 * CVC;
        const float* M1 = Msm + 1 * 3 * CVC + j2 * CVC;
        const float* M2 = Msm + 2 * 3 * CVC + j2 * CVC;
        #pragma unroll 7
        for (int c = 0; c < CVC; c++) {
            l = fmaf(M0[c], cvS[(0 * CVC + c) * 64 + x],
                fmaf(M1[c], cvS[(1 * CVC + c) * 64 + x],
                fmaf(M2[c], cvS[(2 * CVC + c) * 64 + x], l)));
        }
        wsm[j2 * 64 + x] = l;
    }
    __syncthreads();

    // ---- softmax ----
    if (t < 64) {
        float l0 = wsm[t], l1 = wsm[64 + t], l2 = wsm[128 + t];
        float m  = fmaxf(l0, fmaxf(l1, l2));
        float e0 = expf(l0 - m), e1 = expf(l1 - m), e2 = expf(l2 - m);
        float inv = 1.f / (e0 + e1 + e2);
        float w0 = e0 * inv, w1 = e1 * inv, w2 = e2 * inv;
        wsm[t] = w0; wsm[64 + t] = w1; wsm[128 + t] = w2;
        float* wout = out + 2 * NC_ + ((size_t)b * 3 * Hh + h) * Wd + x0 + t;
        wout[0]              = w0;
        wout[(size_t)HW]     = w1;
        wout[(size_t)2 * HW] = w2;
    }
    __syncthreads();

    // ---- final = corr + w·cv ; write final + init_corr ----
    for (int idx = t; idx < CVC * 16; idx += 256) {
        int k = idx >> 4, q = idx & 15;
        float4 corr4 = *(const float4*)&outS[k * 64 + q * 4];
        float4 a0 = *(const float4*)&cvS[(0 * CVC + k) * 64 + q * 4];
        float4 a1 = *(const float4*)&cvS[(1 * CVC + k) * 64 + q * 4];
        float4 a2 = *(const float4*)&cvS[(2 * CVC + k) * 64 + q * 4];
        float4 w0 = *(const float4*)&wsm[0 * 64 + q * 4];
        float4 w1 = *(const float4*)&wsm[1 * 64 + q * 4];
        float4 w2 = *(const float4*)&wsm[2 * 64 + q * 4];
        float4 fin;
        fin.x = corr4.x + fmaf(w0.x, a0.x, fmaf(w1.x, a1.x, w2.x * a2.x));
        fin.y = corr4.y + fmaf(w0.y, a0.y, fmaf(w1.y, a1.y, w2.y * a2.y));
        fin.z = corr4.z + fmaf(w0.z, a0.z, fmaf(w1.z, a1.z, w2.z * a2.z));
        fin.w = corr4.w + fmaf(w0.w, a0.w, fmaf(w1.w, a1.w, w2.w * a2.w));
        size_t off = ((size_t)(b * CVC + k) * Hh + h) * Wd + x0 + q * 4;
        *(float4*)&out[off]       = fin;
        *(float4*)&out[NC_ + off] = corr4;
    }
}

// ---------------- launch ----------------
extern "C" void kernel_launch(void* const* d_in, const int* in_sizes, int n_in,
                              void* d_out, int out_size)
{
    const float* feat_l1 = (const float*)d_in[0];
    const float* feat_r1 = (const float*)d_in[1];
    const float* cv0     = (const float*)d_in[2];
    const float* cv1     = (const float*)d_in[3];
    const float* cv2     = (const float*)d_in[4];
    const float* W_f1    = (const float*)d_in[5];
    const float* b_f1    = (const float*)d_in[6];
    const float* W_f2    = (const float*)d_in[7];
    const float* b_f2    = (const float*)d_in[8];
    const float* W_geo   = (const float*)d_in[9];
    const float* b_geo   = (const float*)d_in[10];
    const float* W_sel   = (const float*)d_in[11];
    const float* b_sel   = (const float*)d_in[12];
    float* out = (float*)d_out;

    prep_kernel<<<65, 256>>>(W_geo, b_geo, W_sel, b_sel, W_f1, W_f2);

    static int fm_set = 0;
    if (!fm_set) {
        cudaFuncSetAttribute(fmap_kernel, cudaFuncAttributeMaxDynamicSharedMemorySize, FM_SMEM_BYTES);
        fm_set = 1;
    }
    fmap_kernel<<<dim3(NPIX / 128, 2), 256, FM_SMEM_BYTES>>>(feat_l1, feat_r1, b_f1, b_f2);

    static int cs_set = 0;
    if (!cs_set) {
        cudaFuncSetAttribute(corrsel_kernel, cudaFuncAttributeMaxDynamicSharedMemorySize, CS_SMEM_BYTES);
        cs_set = 1;
    }
    corrsel_kernel<<<Bn * Hh * (Wd / 64), 256, CS_SMEM_BYTES>>>(cv0, cv1, cv2, out);
}

// round 17
// speedup vs baseline: 1.7426x; 1.1494x over previous
#include <cuda_runtime.h>
#include <cuda_bf16.h>
#include <cuda_fp16.h>
#include <cstdint>
#include <cstddef>

// ---------------- problem constants ----------------
#define Bn   4
#define Cc   128
#define Hh   128
#define Wd   256
#define HW   (Hh*Wd)          // 32768
#define Ff   128
#define CVC  49
#define RAD  24
#define NPIX (Bn*HW)          // 131072
static const size_t NC_ = (size_t)Bn * CVC * HW;  // elements per corr-like tensor

// ---------------- device scratch (static, no allocation) ----------------
// normalized fmaps, fp16 bits, PIXEL-major [B][H][W][F]
__device__ uint16_t g_f1b[(size_t)NPIX * Ff];
__device__ uint16_t g_f2b[(size_t)NPIX * Ff];
__device__ float g_M[9 * CVC];                 // [i][j][c], i=volume, j=logit
__device__ float g_beta[3];
// pre-split W images: hi = fp16(W), lo = bf16(W - hi); padded row stride 136 halfwords
__device__ uint16_t g_W1h[Ff * 136];
__device__ uint16_t g_W1l[Ff * 136];
__device__ uint16_t g_W2h[Ff * 136];
__device__ uint16_t g_W2l[Ff * 136];

// ---------------- helpers ----------------
__device__ __forceinline__ void cp16(void* smem_dst, const void* gmem_src) {
    unsigned int s = (unsigned int)__cvta_generic_to_shared(smem_dst);
    asm volatile("cp.async.cg.shared.global [%0], [%1], 16;" :: "r"(s), "l"(gmem_src));
}
__device__ __forceinline__ void cp_commit() { asm volatile("cp.async.commit_group;"); }
template <int N>
__device__ __forceinline__ void cp_wait() { asm volatile("cp.async.wait_group %0;" :: "n"(N)); }

// bf16 warp MMA m16n8k16, A row-major, B col-major, fp32 accum.
__device__ __forceinline__ void mma16816(float* d, const uint32_t* a, const uint32_t* b) {
    asm volatile("mma.sync.aligned.m16n8k16.row.col.f32.bf16.bf16.f32 "
                 "{%0,%1,%2,%3}, {%4,%5,%6,%7}, {%8,%9}, {%0,%1,%2,%3};"
                 : "+f"(d[0]), "+f"(d[1]), "+f"(d[2]), "+f"(d[3])
                 : "r"(a[0]), "r"(a[1]), "r"(a[2]), "r"(a[3]), "r"(b[0]), "r"(b[1]));
}
// fp16 warp MMA m16n8k16, fp32 accum.
__device__ __forceinline__ void mma16816h(float* d, const uint32_t* a, const uint32_t* b) {
    asm volatile("mma.sync.aligned.m16n8k16.row.col.f32.f16.f16.f32 "
                 "{%0,%1,%2,%3}, {%4,%5,%6,%7}, {%8,%9}, {%0,%1,%2,%3};"
                 : "+f"(d[0]), "+f"(d[1]), "+f"(d[2]), "+f"(d[3])
                 : "r"(a[0]), "r"(a[1]), "r"(a[2]), "r"(a[3]), "r"(b[0]), "r"(b[1]));
}

__device__ __forceinline__ uint32_t pack2h(float a, float b) {
    __half2 h = __floats2half2_rn(a, b); return *(uint32_t*)&h;
}
__device__ __forceinline__ uint32_t pack2b(float a, float b) {
    __nv_bfloat162 h = __floats2bfloat162_rn(a, b); return *(uint32_t*)&h;
}

// ---------------- prep ----------------
// blocks 0..55: M fold, one warp per output (441 warps);
// block 56: beta; blocks 57..64: W hi(fp16)/lo(bf16) split images.
__global__ void prep_kernel(const float* __restrict__ Wgeo, const float* __restrict__ bgeo,
                            const float* __restrict__ Wsel, const float* __restrict__ bsel,
                            const float* __restrict__ WfA,  const float* __restrict__ WfB)
{
    int blk = blockIdx.x, t = threadIdx.x;
    if (blk < 56) {
        int w = blk * 8 + (t >> 5);
        int l = t & 31;
        if (w < 441) {
            int i = w / 147, r = w % 147, j = r / CVC, c = r % CVC;
            float s = 0.f;
            #pragma unroll
            for (int k = 0; k < 3; k++) {
                int m = l + k * 32;
                s += Wsel[j * 288 + i * 96 + m] * Wgeo[m * CVC + c];
            }
            #pragma unroll
            for (int off = 16; off; off >>= 1)
                s += __shfl_xor_sync(0xFFFFFFFF, s, off);
            if (l == 0) g_M[i * 3 * CVC + j * CVC + c] = s;
        }
    } else if (blk == 56) {
        if (t < 3) {
            float s = bsel[t];
            for (int q = 0; q < 288; q++)
                s += Wsel[t * 288 + q] * bgeo[q % 96];
            g_beta[t] = s;
        }
    } else {
        int blk4 = blk - 57;                    // 0..7
        int mat  = blk4 >> 2;
        int part = blk4 & 3;
        const float* src = mat ? WfB : WfA;
        uint16_t* dh = mat ? g_W2h : g_W1h;
        uint16_t* dl = mat ? g_W2l : g_W1l;
        #pragma unroll
        for (int it = 0; it < 16; it++) {
            int idx = part * 4096 + it * 256 + t;   // [o][c]
            int o = idx >> 7, c = idx & 127;
            float v = src[idx];
            __half h = __float2half_rn(v);
            float rv = v - __half2float(h);
            __nv_bfloat16 lo = __float2bfloat16(rv);
            dh[o * 136 + c] = *(uint16_t*)&h;
            dl[o * 136 + c] = *(uint16_t*)&lo;
        }
    }
}

// ---------------- fmap: 2-term mixed HMMA (A_fp16*Wh_fp16 + A_bf16*Wl_bf16) ----------------
#define WH_OFF   0            // uint16[128][136]  34816 B (fp16 Wh)
#define WL_OFF   34816        // uint16[128][136]  34816 B (bf16 Wl)
#define A_OFF    69632        // fp32 [2][32][132] 2x16896 B
#define BIAS_OFF 103424       // fp32[128]
#define SS_OFF   103936       // fp32[128]
#define FM_SMEM_BYTES 104448

extern __shared__ float dynsm[];

__global__ __launch_bounds__(256, 2) void fmap_kernel(
    const float* __restrict__ featA, const float* __restrict__ featB,
    const float* __restrict__ biasA, const float* __restrict__ biasB)
{
    char* smc = (char*)dynsm;
    uint16_t* sWh = (uint16_t*)(smc + WH_OFF);
    uint16_t* sWl = (uint16_t*)(smc + WL_OFF);
    float* sA0   = (float*)(smc + A_OFF);
    float* sA1   = sA0 + 32 * 132;
    float* biasS = (float*)(smc + BIAS_OFF);
    float* ssS   = (float*)(smc + SS_OFF);
    uint16_t* outB = (uint16_t*)smc;          // fp16 stage [px][o], stride 136, reuses W region
    float* stg[2] = {sA0, sA1};

    int which = blockIdx.y;
    const float* feat = which ? featB : featA;
    const float* bias = which ? biasB : biasA;
    const uint16_t* gWh = which ? g_W2h : g_W1h;
    const uint16_t* gWl = which ? g_W2l : g_W1l;
    uint16_t* outp = which ? g_f2b : g_f1b;

    int t    = threadIdx.x;
    int wid  = t >> 5, lane = t & 31;
    int gid  = lane >> 2, tig = lane & 3;
    int warp_m = wid & 3, warp_n = wid >> 2;
    int p0  = blockIdx.x * 128;
    int b   = p0 / HW;
    int rem = p0 % HW;
    const float* fbase = feat + (size_t)b * Cc * HW + rem;

    if (t < 128) { biasS[t] = bias[t]; ssS[t] = 0.f; }

    // A chunk 0 prefetch
    #pragma unroll
    for (int it = 0; it < 4; it++) {
        int idx = t + it * 256;
        int c = idx >> 5, q = idx & 31;
        cp16(&sA0[c * 132 + q * 4], &fbase[(size_t)c * HW + q * 4]);
    }
    cp_commit();

    // W hi/lo: linear 16B copies of pre-split images
    #pragma unroll
    for (int it = 0; it < 17; it++) {
        int idx = t + it * 256;                // 0..4351
        int half = idx >= 2176;
        int i = idx - half * 2176;
        int row = i / 17, seg = i % 17;
        if (half) cp16(sWl + row * 136 + seg * 8, gWl + row * 136 + seg * 8);
        else      cp16(sWh + row * 136 + seg * 8, gWh + row * 136 + seg * 8);
    }
    cp_commit();

    float acc[2][8][4];
    #pragma unroll
    for (int mt = 0; mt < 2; mt++)
        #pragma unroll
        for (int nt = 0; nt < 8; nt++)
            #pragma unroll
            for (int r = 0; r < 4; r++) acc[mt][nt][r] = 0.f;

    int row0 = warp_m * 32 + gid;

    #pragma unroll
    for (int ch = 0; ch < 4; ch++) {
        if (ch < 3) {
            float* dst = stg[(ch + 1) & 1];
            const float* src = fbase + (size_t)(ch + 1) * 32 * HW;
            #pragma unroll
            for (int it = 0; it < 4; it++) {
                int idx = t + it * 256;
                int c = idx >> 5, q = idx & 31;
                cp16(&dst[c * 132 + q * 4], &src[(size_t)c * HW + q * 4]);
            }
            cp_commit();
            cp_wait<1>();
        } else {
            cp_wait<0>();
        }
        __syncthreads();

        const float* A = stg[ch & 1];
        #pragma unroll
        for (int ks = 0; ks < 2; ks++) {
            int kb = ks * 16 + 2 * tig;
            uint32_t ah[2][4], ab[2][4];
            #pragma unroll
            for (int mt = 0; mt < 2; mt++) {
                int row = row0 + mt * 16;
                float f0 = A[kb * 132 + row],        f1 = A[(kb + 1) * 132 + row];
                float f2 = A[kb * 132 + row + 8],    f3 = A[(kb + 1) * 132 + row + 8];
                float f4 = A[(kb + 8) * 132 + row],  f5 = A[(kb + 9) * 132 + row];
                float f6 = A[(kb + 8) * 132 + row + 8], f7 = A[(kb + 9) * 132 + row + 8];
                ah[mt][0] = pack2h(f0, f1);  ab[mt][0] = pack2b(f0, f1);
                ah[mt][1] = pack2h(f2, f3);  ab[mt][1] = pack2b(f2, f3);
                ah[mt][2] = pack2h(f4, f5);  ab[mt][2] = pack2b(f4, f5);
                ah[mt][3] = pack2h(f6, f7);  ab[mt][3] = pack2b(f6, f7);
            }
            int kw = ch * 32 + kb;
            #pragma unroll
            for (int nt = 0; nt < 8; nt++) {
                int orow = warp_n * 64 + nt * 8 + gid;
                uint32_t wh[2], wl[2];
                wh[0] = *(const uint32_t*)(sWh + orow * 136 + kw);
                wh[1] = *(const uint32_t*)(sWh + orow * 136 + kw + 8);
                wl[0] = *(const uint32_t*)(sWl + orow * 136 + kw);
                wl[1] = *(const uint32_t*)(sWl + orow * 136 + kw + 8);
                mma16816h(acc[0][nt], ah[0], wh);
                mma16816 (acc[0][nt], ab[0], wl);
                mma16816h(acc[1][nt], ah[1], wh);
                mma16816 (acc[1][nt], ab[1], wl);
            }
        }
        __syncthreads();
    }

    // ---- epilogue: bias, per-pixel L2 norm, fp16 pixel-major staged stores ----
    #pragma unroll
    for (int nt = 0; nt < 8; nt++) {
        int ob2 = warp_n * 64 + nt * 8 + 2 * tig;
        float bi0 = biasS[ob2], bi1 = biasS[ob2 + 1];
        #pragma unroll
        for (int mt = 0; mt < 2; mt++) {
            acc[mt][nt][0] += bi0; acc[mt][nt][1] += bi1;
            acc[mt][nt][2] += bi0; acc[mt][nt][3] += bi1;
        }
    }

    float s0[2] = {0.f, 0.f}, s1[2] = {0.f, 0.f};
    #pragma unroll
    for (int mt = 0; mt < 2; mt++)
        #pragma unroll
        for (int nt = 0; nt < 8; nt++) {
            s0[mt] += acc[mt][nt][0] * acc[mt][nt][0] + acc[mt][nt][1] * acc[mt][nt][1];
            s1[mt] += acc[mt][nt][2] * acc[mt][nt][2] + acc[mt][nt][3] * acc[mt][nt][3];
        }
    #pragma unroll
    for (int off = 1; off <= 2; off <<= 1) {
        s0[0] += __shfl_xor_sync(0xFFFFFFFF, s0[0], off);
        s0[1] += __shfl_xor_sync(0xFFFFFFFF, s0[1], off);
        s1[0] += __shfl_xor_sync(0xFFFFFFFF, s1[0], off);
        s1[1] += __shfl_xor_sync(0xFFFFFFFF, s1[1], off);
    }
    if (tig == 0) {
        #pragma unroll
        for (int mt = 0; mt < 2; mt++) {
            int px = warp_m * 32 + mt * 16 + gid;
            atomicAdd(&ssS[px], s0[mt]);
            atomicAdd(&ssS[px + 8], s1[mt]);
        }
    }
    __syncthreads();
    if (t < 128) ssS[t] = 1.f / (sqrtf(ssS[t]) + 1e-8f);
    __syncthreads();

    #pragma unroll
    for (int mt = 0; mt < 2; mt++) {
        int px = warp_m * 32 + mt * 16 + gid;
        float iv0 = ssS[px], iv1 = ssS[px + 8];
        #pragma unroll
        for (int nt = 0; nt < 8; nt++) {
            int o = warp_n * 64 + nt * 8 + 2 * tig;     // even
            *(uint32_t*)(outB + px * 136 + o) =
                pack2h(acc[mt][nt][0] * iv0, acc[mt][nt][1] * iv0);
            *(uint32_t*)(outB + (px + 8) * 136 + o) =
                pack2h(acc[mt][nt][2] * iv1, acc[mt][nt][3] * iv1);
        }
    }
    __syncthreads();

    #pragma unroll
    for (int it = 0; it < 8; it++) {
        int idx = t + it * 256;                // 2048 uint4 (8 fp16 each)
        int px = idx >> 4, seg = idx & 15;
        uint4 v = *(const uint4*)(outB + px * 136 + seg * 8);
        *(uint4*)(outp + ((size_t)p0 + px) * Ff + seg * 8) = v;
    }
}

// ---------------- fused correlation(HMMA) + selector (R16-verbatim) ----------------
#define CS_SB  4352
#define CS_CV  11968
#define CS_WS  21376
#define CS_MS  21568
#define CS_BT  22009
#define CS_SMEM_BYTES (22012 * 4)

__global__ __launch_bounds__(256, 2) void corrsel_kernel(const float* __restrict__ cv0,
                                                         const float* __restrict__ cv1,
                                                         const float* __restrict__ cv2,
                                                         float* __restrict__ out)
{
    uint16_t* sA = (uint16_t*)dynsm;
    uint16_t* sB = (uint16_t*)(dynsm + CS_SB);
    float* cvS   = dynsm + CS_CV;
    float* wsm   = dynsm + CS_WS;
    float* Msm   = dynsm + CS_MS;
    float* betaS = dynsm + CS_BT;
    float* outS  = dynsm;

    int t   = threadIdx.x;
    int blk = blockIdx.x;
    int bh  = blk >> 2;
    int x0  = (blk & 3) * 64;
    int b   = bh / Hh, h = bh % Hh;

    const uint16_t* f1 = g_f1b + ((size_t)bh * Wd + x0) * Ff;   // pixel-major rows
    const uint16_t* f2 = g_f2b + (size_t)bh * Wd * Ff;

    // group 1: A + B fp16 tiles
    for (int idx = t; idx < 1024; idx += 256) {        // 64 px x 16 seg
        int px = idx >> 4, seg = idx & 15;
        cp16(sA + px * 136 + seg * 8, f1 + (size_t)px * Ff + seg * 8);
    }
    for (int idx = t; idx < 1792; idx += 256) {        // 112 r x 16 seg
        int r = idx >> 4, seg = idx & 15;
        int xg = x0 - RAD + r;
        if (xg >= 0 && xg < Wd)
            cp16(sB + r * 136 + seg * 8, f2 + (size_t)xg * Ff + seg * 8);
        else
            *(uint4*)(sB + r * 136 + seg * 8) = make_uint4(0, 0, 0, 0);
    }
    cp_commit();

    // group 2: cv tiles
    for (int idx = t; idx < 3 * CVC * 16; idx += 256) {
        int v = idx / (CVC * 16);
        int r = idx - v * (CVC * 16);
        int c = r >> 4, q = r & 15;
        const float* src = (v == 0 ? cv0 : (v == 1 ? cv1 : cv2));
        cp16(&cvS[(v * CVC + c) * 64 + q * 4],
             &src[((size_t)(b * CVC + c) * Hh + h) * Wd + x0 + q * 4]);
    }
    cp_commit();

    // M/beta plain loads (region not reused)
    for (int i = t; i < 9 * CVC; i += 256) Msm[i] = g_M[i];
    if (t < 3) betaS[t] = g_beta[t];

    cp_wait<1>();          // A+B tiles resident
    __syncthreads();

    // ---- Gram via fp16 HMMA: out[xl, r] = sum_ch A[xl][ch] * B[r][ch] ----
    int wid = t >> 5, lane = t & 31;
    int gid = lane >> 2, tig = lane & 3;
    int wm = wid & 3, wn = wid >> 2;
    int m0 = wm * 16;

    float acc[4][4];
    #pragma unroll
    for (int nt = 0; nt < 4; nt++)
        #pragma unroll
        for (int r = 0; r < 4; r++) acc[nt][r] = 0.f;

    #pragma unroll
    for (int kt = 0; kt < 8; kt++) {
        int kb = kt * 16 + 2 * tig;
        uint32_t a[4];
        a[0] = *(const uint32_t*)(sA + (m0 + gid) * 136 + kb);
        a[1] = *(const uint32_t*)(sA + (m0 + gid + 8) * 136 + kb);
        a[2] = *(const uint32_t*)(sA + (m0 + gid) * 136 + kb + 8);
        a[3] = *(const uint32_t*)(sA + (m0 + gid + 8) * 136 + kb + 8);
        #pragma unroll
        for (int nt = 0; nt < 4; nt++) {
            int rb = m0 + wn * 32 + nt * 8;
            uint32_t bf[2];
            bf[0] = *(const uint32_t*)(sB + (rb + gid) * 136 + kb);
            bf[1] = *(const uint32_t*)(sB + (rb + gid) * 136 + kb + 8);
            mma16816h(acc[nt], a, bf);
        }
    }
    __syncthreads();       // sA reads done; outS may overwrite

    // scatter to outS[k*64 + xl], k = xl + 48 - r
    #pragma unroll
    for (int nt = 0; nt < 4; nt++) {
        int rb = m0 + wn * 32 + nt * 8 + 2 * tig;
        int xl0 = m0 + gid;
        int k00 = xl0 + 48 - rb;        // c0: (xl0, rb)
        if (k00 >= 0 && k00 <= 48)      outS[k00 * 64 + xl0]           = acc[nt][0];
        if (k00 - 1 >= 0 && k00 - 1 <= 48) outS[(k00 - 1) * 64 + xl0]  = acc[nt][1];
        int k20 = k00 + 8;              // c2: (xl0+8, rb)
        if (k20 >= 0 && k20 <= 48)      outS[k20 * 64 + xl0 + 8]       = acc[nt][2];
        if (k20 - 1 >= 0 && k20 - 1 <= 48) outS[(k20 - 1) * 64 + xl0 + 8] = acc[nt][3];
    }
    cp_wait<0>();          // cv resident
    __syncthreads();

    // ---- folded logits (192 threads: 3 logits x 64 px) ----
    if (t < 192) {
        int j2 = t >> 6;
        int x  = t & 63;
        float l = betaS[j2];
        const float* M0 = Msm + 0 * 3 * CVC + j2 * CVC;
        const float* M1 = Msm + 1 * 3 * CVC + j2 * CVC;
        const float* M2 = Msm + 2 * 3 * CVC + j2 * CVC;
        #pragma unroll 7
        for (int c = 0; c < CVC; c++) {
            l = fmaf(M0[c], cvS[(0 * CVC + c) * 64 + x],
                fmaf(M1[c], cvS[(1 * CVC + c) * 64 + x],
                fmaf(M2[c], cvS[(2 * CVC + c) * 64 + x], l)));
        }
        wsm[j2 * 64 + x] = l;
    }
    __syncthreads();

    // ---- softmax ----
    if (t < 64) {
        float l0 = wsm[t], l1 = wsm[64 + t], l2 = wsm[128 + t];
        float m  = fmaxf(l0, fmaxf(l1, l2));
        float e0 = expf(l0 - m), e1 = expf(l1 - m), e2 = expf(l2 - m);
        float inv = 1.f / (e0 + e1 + e2);
        float w0 = e0 * inv, w1 = e1 * inv, w2 = e2 * inv;
        wsm[t] = w0; wsm[64 + t] = w1; wsm[128 + t] = w2;
        float* wout = out + 2 * NC_ + ((size_t)b * 3 * Hh + h) * Wd + x0 + t;
        wout[0]              = w0;
        wout[(size_t)HW]     = w1;
        wout[(size_t)2 * HW] = w2;
    }
    __syncthreads();

    // ---- final = corr + w·cv ; write final + init_corr ----
    for (int idx = t; idx < CVC * 16; idx += 256) {
        int k = idx >> 4, q = idx & 15;
        float4 corr4 = *(const float4*)&outS[k * 64 + q * 4];
        float4 a0 = *(const float4*)&cvS[(0 * CVC + k) * 64 + q * 4];
        float4 a1 = *(const float4*)&cvS[(1 * CVC + k) * 64 + q * 4];
        float4 a2 = *(const float4*)&cvS[(2 * CVC + k) * 64 + q * 4];
        float4 w0 = *(const float4*)&wsm[0 * 64 + q * 4];
        float4 w1 = *(const float4*)&wsm[1 * 64 + q * 4];
        float4 w2 = *(const float4*)&wsm[2 * 64 + q * 4];
        float4 fin;
        fin.x = corr4.x + fmaf(w0.x, a0.x, fmaf(w1.x, a1.x, w2.x * a2.x));
        fin.y = corr4.y + fmaf(w0.y, a0.y, fmaf(w1.y, a1.y, w2.y * a2.y));
        fin.z = corr4.z + fmaf(w0.z, a0.z, fmaf(w1.z, a1.z, w2.z * a2.z));
        fin.w = corr4.w + fmaf(w0.w, a0.w, fmaf(w1.w, a1.w, w2.w * a2.w));
        size_t off = ((size_t)(b * CVC + k) * Hh + h) * Wd + x0 + q * 4;
        *(float4*)&out[off]       = fin;
        *(float4*)&out[NC_ + off] = corr4;
    }
}

// ---------------- launch ----------------
extern "C" void kernel_launch(void* const* d_in, const int* in_sizes, int n_in,
                              void* d_out, int out_size)
{
    const float* feat_l1 = (const float*)d_in[0];
    const float* feat_r1 = (const float*)d_in[1];
    const float* cv0     = (const float*)d_in[2];
    const float* cv1     = (const float*)d_in[3];
    const float* cv2     = (const float*)d_in[4];
    const float* W_f1    = (const float*)d_in[5];
    const float* b_f1    = (const float*)d_in[6];
    const float* W_f2    = (const float*)d_in[7];
    const float* b_f2    = (const float*)d_in[8];
    const float* W_geo   = (const float*)d_in[9];
    const float* b_geo   = (const float*)d_in[10];
    const float* W_sel   = (const float*)d_in[11];
    const float* b_sel   = (const float*)d_in[12];
    float* out = (float*)d_out;

    prep_kernel<<<65, 256>>>(W_geo, b_geo, W_sel, b_sel, W_f1, W_f2);

    static int fm_set = 0;
    if (!fm_set) {
        cudaFuncSetAttribute(fmap_kernel, cudaFuncAttributeMaxDynamicSharedMemorySize, FM_SMEM_BYTES);
        fm_set = 1;
    }
    fmap_kernel<<<dim3(NPIX / 128, 2), 256, FM_SMEM_BYTES>>>(feat_l1, feat_r1, b_f1, b_f2);

    static int cs_set = 0;
    if (!cs_set) {
        cudaFuncSetAttribute(corrsel_kernel, cudaFuncAttributeMaxDynamicSharedMemorySize, CS_SMEM_BYTES);
        cs_set = 1;
    }
    corrsel_kernel<<<Bn * Hh * (Wd / 64), 256, CS_SMEM_BYTES>>>(cv0, cv1, cv2, out);
}